// round 2
// baseline (speedup 1.0000x reference)
#include <cuda_runtime.h>
#include <math.h>

#define NN 2048
#define CC 16
#define FF 1024
#define NHEADS 4
#define KF 4096
#define EE 16384
#define NPIX 131072
#define BNEPS 1e-5f

// ---------------- scratch (static device memory; no allocation) ----------------
__device__ float d_yf[NN * FF];          // 8 MB   BN1-folded node features
__device__ float d_xl[NN * KF];          // 33.5MB xl = yf@wl+bl
__device__ float d_xr[NN * KF];          // 33.5MB xr = yf@wr+br
__device__ float d_Sx[16];
__device__ float d_Sxx[136];
__device__ float d_A[256];               // folded conv1+BN1 weight
__device__ float d_dv[16];               // folded conv1+BN1 bias
__device__ int   d_cnt[NN];
__device__ int   d_rowstart[NN + 1];
__device__ int   d_cursor[NN];
__device__ int   d_esrc[EE + NN];
__device__ float d_b2sum[16], d_b2sq[16], d_sc2[16], d_sh2[16];

// ---------------- init / zero accumulators ----------------
__global__ void k_init() {
    int t = threadIdx.x;
    for (int i = t; i < NN; i += 256) d_cnt[i] = 1;     // self-loop
    if (t < 16) { d_Sx[t] = 0.f; d_b2sum[t] = 0.f; d_b2sq[t] = 0.f; }
    for (int i = t; i < 136; i += 256) d_Sxx[i] = 0.f;
}

// ---------------- channel stats of x (for analytic BN1 fold) ----------------
__global__ __launch_bounds__(256) void k_stats(const float* __restrict__ x) {
    __shared__ float sm[16][513];
    int t = threadIdx.x;
    int base = blockIdx.x * 512;
    for (int i = t; i < 16 * 512; i += 256) {
        int c = i >> 9, s = i & 511;
        int q = base + s;
        sm[c][s] = x[(q >> 6) * 1024 + c * 64 + (q & 63)];
    }
    __syncthreads();
    if (t < 16) {
        float acc = 0.f;
        #pragma unroll 8
        for (int s = 0; s < 512; s++) acc += sm[t][s];
        atomicAdd(&d_Sx[t], acc);
    } else if (t < 152) {
        int p = t - 16;
        int c = 0, r = p;
        while (r >= 16 - c) { r -= 16 - c; c++; }
        int c2 = c + r;
        float acc = 0.f;
        #pragma unroll 8
        for (int s = 0; s < 512; s++) acc += sm[c][s] * sm[c2][s];
        atomicAdd(&d_Sxx[p], acc);
    }
}

// ---------------- edge histogram ----------------
__global__ void k_hist(const int* __restrict__ ei) {
    int e = blockIdx.x * blockDim.x + threadIdx.x;
    if (e < EE) {
        int s = ei[e], d = ei[EE + e];
        if (s != d) atomicAdd(&d_cnt[d], 1);
    }
}

// ---------------- fold conv1+BN1 into affine A, dv ----------------
__global__ void k_bnfold(const float* __restrict__ w1, const float* __restrict__ b1,
                         const float* __restrict__ g1, const float* __restrict__ be1) {
    __shared__ float mx[16], cov[16][16];
    int t = threadIdx.x;
    if (t < 16) mx[t] = d_Sx[t] * (1.0f / NPIX);
    __syncthreads();
    if (t < 136) {
        int c = 0, r = t;
        while (r >= 16 - c) { r -= 16 - c; c++; }
        int c2 = c + r;
        float cv = d_Sxx[t] * (1.0f / NPIX) - mx[c] * mx[c2];
        cov[c][c2] = cv; cov[c2][c] = cv;
    }
    __syncthreads();
    if (t < 16) {
        int o = t;
        float m = b1[o], var = 0.f;
        for (int c = 0; c < 16; c++) {
            float wc = w1[o * 16 + c];
            m += wc * mx[c];
            for (int c2 = 0; c2 < 16; c2++) var += wc * w1[o * 16 + c2] * cov[c][c2];
        }
        float rs = rsqrtf(var + BNEPS) * g1[o];
        for (int c = 0; c < 16; c++) d_A[o * 16 + c] = w1[o * 16 + c] * rs;
        d_dv[o] = (b1[o] - m) * rs + be1[o];
    }
}

// ---------------- prefix sum -> CSR rowstart/cursor ----------------
__global__ void k_scan() {
    __shared__ int bufA[2048], bufB[2048];
    int t = threadIdx.x;  // 1024 threads
    bufA[t] = d_cnt[t]; bufA[t + 1024] = d_cnt[t + 1024];
    __syncthreads();
    int* src = bufA; int* dst = bufB;
    for (int off = 1; off < 2048; off <<= 1) {
        for (int i = t; i < 2048; i += 1024) {
            int v = src[i];
            if (i >= off) v += src[i - off];
            dst[i] = v;
        }
        __syncthreads();
        int* tmp = src; src = dst; dst = tmp;
    }
    for (int i = t; i < 2048; i += 1024) {
        int ex = (i == 0) ? 0 : src[i - 1];
        d_rowstart[i] = ex; d_cursor[i] = ex;
    }
    if (t == 0) d_rowstart[2048] = src[2047];
}

// ---------------- scatter edges into CSR ----------------
__global__ void k_scatter(const int* __restrict__ ei) {
    int i = blockIdx.x * blockDim.x + threadIdx.x;
    if (i < NN) {
        int pos = atomicAdd(&d_cursor[i], 1);
        d_esrc[pos] = i;
    } else if (i < NN + EE) {
        int e = i - NN;
        int s = ei[e], d = ei[EE + e];
        if (s != d) { int pos = atomicAdd(&d_cursor[d], 1); d_esrc[pos] = s; }
    }
}

// ---------------- fused conv1+BN1 apply: yf = A*x + dv ----------------
__global__ __launch_bounds__(256) void k_yf(const float* __restrict__ x) {
    __shared__ float As[256], dvs[16];
    int t = threadIdx.x;
    if (t < 256) As[t] = d_A[t];
    if (t < 16) dvs[t] = d_dv[t];
    __syncthreads();
    int q = blockIdx.x * 256 + t;   // pixel id, 131072 total
    int n = q >> 6, p = q & 63;
    float xv[16];
    #pragma unroll
    for (int c = 0; c < 16; c++) xv[c] = x[n * 1024 + c * 64 + p];
    #pragma unroll
    for (int o = 0; o < 16; o++) {
        float s = dvs[o];
        #pragma unroll
        for (int c = 0; c < 16; c++) s += As[o * 16 + c] * xv[c];
        d_yf[n * 1024 + o * 64 + p] = s;
    }
}

// ---------------- SGEMM: C = d_yf[2048,1024] @ B[1024,4096] + bias ----------------
__global__ __launch_bounds__(256, 2) void k_sgemm(const float* __restrict__ B,
                                                  const float* __restrict__ bias,
                                                  int which) {
    const int K = 1024, NCOL = 4096;
    __shared__ float As[8][128];
    __shared__ float Bs[8][128];
    float* C = which ? d_xr : d_xl;
    const float* A = d_yf;
    int tid = threadIdx.x;
    int bm = blockIdx.y * 128, bn = blockIdx.x * 128;
    int tr = tid >> 4, tc = tid & 15;
    float acc[8][8];
    #pragma unroll
    for (int i = 0; i < 8; i++)
        #pragma unroll
        for (int j = 0; j < 8; j++) acc[i][j] = 0.f;

    int a_r = tid >> 1, a_c = (tid & 1) * 4;
    int b_r = tid >> 5, b_c = (tid & 31) * 4;
    const float* Ab = A + (bm + a_r) * K + a_c;
    const float* Bb = B + b_r * NCOL + bn + b_c;

    for (int k0 = 0; k0 < K; k0 += 8) {
        float4 av = *(const float4*)(Ab + k0);
        As[a_c + 0][a_r] = av.x; As[a_c + 1][a_r] = av.y;
        As[a_c + 2][a_r] = av.z; As[a_c + 3][a_r] = av.w;
        *(float4*)(&Bs[b_r][b_c]) = *(const float4*)(Bb + k0 * NCOL);
        __syncthreads();
        #pragma unroll
        for (int kk = 0; kk < 8; kk++) {
            float a[8], b[8];
            *(float4*)&a[0] = *(const float4*)&As[kk][tr * 8];
            *(float4*)&a[4] = *(const float4*)&As[kk][tr * 8 + 4];
            *(float4*)&b[0] = *(const float4*)&Bs[kk][tc * 8];
            *(float4*)&b[4] = *(const float4*)&Bs[kk][tc * 8 + 4];
            #pragma unroll
            for (int i = 0; i < 8; i++)
                #pragma unroll
                for (int j = 0; j < 8; j++) acc[i][j] += a[i] * b[j];
        }
        __syncthreads();
    }
    #pragma unroll
    for (int i = 0; i < 8; i++) {
        int row = bm + tr * 8 + i;
        #pragma unroll
        for (int j = 0; j < 8; j += 4) {
            int col = bn + tc * 8 + j;
            float4 o;
            o.x = acc[i][j + 0] + bias[col + 0];
            o.y = acc[i][j + 1] + bias[col + 1];
            o.z = acc[i][j + 2] + bias[col + 2];
            o.w = acc[i][j + 3] + bias[col + 3];
            *(float4*)(&C[row * NCOL + col]) = o;
        }
    }
}

// ---------------- fused GAT (online softmax) + conv2 + BN2 stats ----------------
__global__ __launch_bounds__(256) void k_gat(const float* __restrict__ att,
                                             const float* __restrict__ biasg,
                                             const float* __restrict__ w2,
                                             const float* __restrict__ b2,
                                             float* __restrict__ outp) {
    __shared__ float gs[4096];
    __shared__ float w2s[1024];
    __shared__ float red[8][4];
    __shared__ float logit_s[4];
    __shared__ float ssum[16], ssq[16];
    int n = blockIdx.x;
    int t = threadIdx.x;
    int lane = t & 31, warp = t >> 5;

    for (int i = t; i < 1024; i += 256) w2s[i] = w2[i];
    if (t < 16) { ssum[t] = 0.f; ssq[t] = 0.f; }

    float attv[16], xrv[16], acc[16];
    #pragma unroll
    for (int j = 0; j < 16; j++) {
        attv[j] = att[t + 256 * j];
        xrv[j]  = d_xr[n * 4096 + t + 256 * j];
        acc[j]  = 0.f;
    }
    float mh[4] = {-3.0e38f, -3.0e38f, -3.0e38f, -3.0e38f};
    float lh[4] = {0.f, 0.f, 0.f, 0.f};

    int beg = d_rowstart[n], end = d_rowstart[n + 1];
    for (int e = beg; e < end; e++) {
        int src = d_esrc[e];
        const float* xls = d_xl + src * 4096;
        float xlv[16];
        #pragma unroll
        for (int j = 0; j < 16; j++) xlv[j] = xls[t + 256 * j];

        float part[4] = {0.f, 0.f, 0.f, 0.f};
        #pragma unroll
        for (int j = 0; j < 16; j++) {
            float z = xlv[j] + xrv[j];
            float lr = z > 0.f ? z : 0.2f * z;
            part[j >> 2] += attv[j] * lr;
        }
        #pragma unroll
        for (int off = 16; off > 0; off >>= 1) {
            #pragma unroll
            for (int h = 0; h < 4; h++)
                part[h] += __shfl_down_sync(0xffffffffu, part[h], off);
        }
        if (lane == 0) {
            #pragma unroll
            for (int h = 0; h < 4; h++) red[warp][h] = part[h];
        }
        __syncthreads();
        if (t < 4) {
            float v = 0.f;
            #pragma unroll
            for (int w = 0; w < 8; w++) v += red[w][t];
            logit_s[t] = v;
        }
        __syncthreads();
        float sc[4], cf[4];
        #pragma unroll
        for (int h = 0; h < 4; h++) {
            float L = logit_s[h];
            float nm = fmaxf(mh[h], L);
            sc[h] = __expf(mh[h] - nm);
            cf[h] = __expf(L - nm);
            mh[h] = nm;
            lh[h] = lh[h] * sc[h] + cf[h];
        }
        #pragma unroll
        for (int j = 0; j < 16; j++)
            acc[j] = acc[j] * sc[j >> 2] + cf[j >> 2] * xlv[j];
    }

    // g = acc/l + bias_gat  -> shared
    #pragma unroll
    for (int j = 0; j < 16; j++) {
        float g = acc[j] / lh[j >> 2] + biasg[t + 256 * j];
        gs[t + 256 * j] = g;
    }
    __syncthreads();

    // conv2 (1x1 over 64 channels) + BN2 partial stats
    #pragma unroll
    for (int i = 0; i < 4; i++) {
        int oidx = t + 256 * i;
        int c = oidx >> 6, p = oidx & 63;
        float s = b2[c];
        #pragma unroll 16
        for (int ch = 0; ch < 64; ch++) s += w2s[c * 64 + ch] * gs[ch * 64 + p];
        outp[n * 1024 + oidx] = s;
        float vs = s, vq = s * s;
        #pragma unroll
        for (int off = 16; off > 0; off >>= 1) {
            vs += __shfl_down_sync(0xffffffffu, vs, off);
            vq += __shfl_down_sync(0xffffffffu, vq, off);
        }
        if (lane == 0) { atomicAdd(&ssum[c], vs); atomicAdd(&ssq[c], vq); }
    }
    __syncthreads();
    if (t < 16) {
        atomicAdd(&d_b2sum[t], ssum[t]);
        atomicAdd(&d_b2sq[t], ssq[t]);
    }
}

// ---------------- BN2 finalize ----------------
__global__ void k_bn2fin(const float* __restrict__ g2, const float* __restrict__ be2) {
    int t = threadIdx.x;
    if (t < 16) {
        float mean = d_b2sum[t] * (1.0f / NPIX);
        float var = d_b2sq[t] * (1.0f / NPIX) - mean * mean;
        float sc = g2[t] * rsqrtf(var + BNEPS);
        d_sc2[t] = sc;
        d_sh2[t] = be2[t] - mean * sc;
    }
}

// ---------------- apply BN2 + residual ----------------
__global__ void k_final(const float* __restrict__ x, float* __restrict__ o) {
    int i = blockIdx.x * blockDim.x + threadIdx.x;
    if (i < NN * 1024) {
        int c = (i >> 6) & 15;
        o[i] = o[i] * d_sc2[c] + d_sh2[c] + x[i];
    }
}

// ---------------- launch ----------------
extern "C" void kernel_launch(void* const* d_in, const int* in_sizes, int n_in,
                              void* d_out, int out_size) {
    const float* x    = (const float*)d_in[0];
    const int*   ei   = (const int*)  d_in[1];
    const float* w1   = (const float*)d_in[2];
    const float* b1   = (const float*)d_in[3];
    const float* g1   = (const float*)d_in[4];
    const float* be1  = (const float*)d_in[5];
    const float* wl   = (const float*)d_in[6];
    const float* bl   = (const float*)d_in[7];
    const float* wr   = (const float*)d_in[8];
    const float* br   = (const float*)d_in[9];
    const float* att  = (const float*)d_in[10];
    const float* bg   = (const float*)d_in[11];
    const float* w2   = (const float*)d_in[12];
    const float* b2   = (const float*)d_in[13];
    const float* g2   = (const float*)d_in[14];
    const float* be2  = (const float*)d_in[15];
    float* outp = (float*)d_out;

    k_init<<<1, 256>>>();
    k_stats<<<256, 256>>>(x);
    k_hist<<<64, 256>>>(ei);
    k_bnfold<<<1, 256>>>(w1, b1, g1, be1);
    k_scan<<<1, 1024>>>();
    k_scatter<<<(NN + EE + 255) / 256, 256>>>(ei);
    k_yf<<<512, 256>>>(x);
    dim3 gg(32, 16);
    k_sgemm<<<gg, 256>>>(wl, bl, 0);
    k_sgemm<<<gg, 256>>>(wr, br, 1);
    k_gat<<<NN, 256>>>(att, bg, w2, b2, outp);
    k_bn2fin<<<1, 32>>>(g2, be2);
    k_final<<<8192, 256>>>(x, outp);
}

// round 4
// speedup vs baseline: 2.2618x; 2.2618x over previous
#include <cuda_runtime.h>
#include <cuda_bf16.h>
#include <math.h>
#include <cstdint>

#define NN 2048
#define CC 16
#define FF 1024
#define NHEADS 4
#define KF 4096
#define EE 16384
#define NPIX 131072
#define BNEPS 1e-5f
#define KCAT 3072

// ---------------- scratch (static device memory; no allocation) ----------------
__device__ __nv_bfloat16 d_Acat[NN * KCAT];      // 12.6 MB [Ahi | Ahi | Alo]
__device__ __nv_bfloat16 d_Bl[KF * KCAT];        // 25.2 MB [Bhi | Blo | Bhi] (transposed wl)
__device__ __nv_bfloat16 d_Br[KF * KCAT];        // 25.2 MB (transposed wr)
__device__ float d_xl[NN * KF];                  // 33.5MB xl = yf@wl+bl
__device__ float d_xr[NN * KF];                  // 33.5MB xr = yf@wr+br
__device__ float d_Sx[16];
__device__ float d_Sxx[136];
__device__ float d_A[256];
__device__ float d_dv[16];
__device__ int   d_cnt[NN];
__device__ int   d_rowstart[NN + 1];
__device__ int   d_cursor[NN];
__device__ int   d_esrc[EE + NN];
__device__ float d_b2sum[16], d_b2sq[16], d_sc2[16], d_sh2[16];

// ---------------- helpers (all baseline sm_80+ PTX; no arch-'a' features) ----------------
__device__ __forceinline__ uint32_t smem_u32(const void* p) {
    uint32_t a;
    asm("{ .reg .u64 t; cvta.to.shared.u64 t, %1; cvt.u32.u64 %0, t; }" : "=r"(a) : "l"(p));
    return a;
}
__device__ __forceinline__ void cp16(uint32_t dst, const void* src) {
    asm volatile("cp.async.cg.shared.global [%0], [%1], 16;" :: "r"(dst), "l"(src) : "memory");
}
__device__ __forceinline__ void ldm4(uint32_t* r, uint32_t addr) {
    asm volatile("ldmatrix.sync.aligned.m8n8.x4.shared.b16 {%0,%1,%2,%3}, [%4];"
                 : "=r"(r[0]), "=r"(r[1]), "=r"(r[2]), "=r"(r[3]) : "r"(addr));
}
__device__ __forceinline__ void mma16816(float* d, const uint32_t* a, uint32_t b0, uint32_t b1) {
    asm volatile("mma.sync.aligned.m16n8k16.row.col.f32.bf16.bf16.f32 "
                 "{%0,%1,%2,%3}, {%4,%5,%6,%7}, {%8,%9}, {%0,%1,%2,%3};"
                 : "+f"(d[0]), "+f"(d[1]), "+f"(d[2]), "+f"(d[3])
                 : "r"(a[0]), "r"(a[1]), "r"(a[2]), "r"(a[3]), "r"(b0), "r"(b1));
}

// ---------------- init / zero accumulators ----------------
__global__ void k_init() {
    int t = threadIdx.x;
    for (int i = t; i < NN; i += 256) d_cnt[i] = 1;     // self-loop
    if (t < 16) { d_Sx[t] = 0.f; d_b2sum[t] = 0.f; d_b2sq[t] = 0.f; }
    for (int i = t; i < 136; i += 256) d_Sxx[i] = 0.f;
}

// ---------------- channel stats of x (for analytic BN1 fold) ----------------
__global__ __launch_bounds__(256) void k_stats(const float* __restrict__ x) {
    __shared__ float sm[16][513];
    int t = threadIdx.x;
    int base = blockIdx.x * 512;
    for (int i = t; i < 16 * 512; i += 256) {
        int c = i >> 9, s = i & 511;
        int q = base + s;
        sm[c][s] = x[(q >> 6) * 1024 + c * 64 + (q & 63)];
    }
    __syncthreads();
    if (t < 16) {
        float acc = 0.f;
        #pragma unroll 8
        for (int s = 0; s < 512; s++) acc += sm[t][s];
        atomicAdd(&d_Sx[t], acc);
    } else if (t < 152) {
        int p = t - 16;
        int c = 0, r = p;
        while (r >= 16 - c) { r -= 16 - c; c++; }
        int c2 = c + r;
        float acc = 0.f;
        #pragma unroll 8
        for (int s = 0; s < 512; s++) acc += sm[c][s] * sm[c2][s];
        atomicAdd(&d_Sxx[p], acc);
    }
}

// ---------------- edge histogram ----------------
__global__ void k_hist(const int* __restrict__ ei) {
    int e = blockIdx.x * blockDim.x + threadIdx.x;
    if (e < EE) {
        int s = ei[e], d = ei[EE + e];
        if (s != d) atomicAdd(&d_cnt[d], 1);
    }
}

// ---------------- fold conv1+BN1 into affine A, dv ----------------
__global__ void k_bnfold(const float* __restrict__ w1, const float* __restrict__ b1,
                         const float* __restrict__ g1, const float* __restrict__ be1) {
    __shared__ float mx[16], cov[16][16];
    int t = threadIdx.x;
    if (t < 16) mx[t] = d_Sx[t] * (1.0f / NPIX);
    __syncthreads();
    if (t < 136) {
        int c = 0, r = t;
        while (r >= 16 - c) { r -= 16 - c; c++; }
        int c2 = c + r;
        float cv = d_Sxx[t] * (1.0f / NPIX) - mx[c] * mx[c2];
        cov[c][c2] = cv; cov[c2][c] = cv;
    }
    __syncthreads();
    if (t < 16) {
        int o = t;
        float m = b1[o], var = 0.f;
        for (int c = 0; c < 16; c++) {
            float wc = w1[o * 16 + c];
            m += wc * mx[c];
            for (int c2 = 0; c2 < 16; c2++) var += wc * w1[o * 16 + c2] * cov[c][c2];
        }
        float rs = rsqrtf(var + BNEPS) * g1[o];
        for (int c = 0; c < 16; c++) d_A[o * 16 + c] = w1[o * 16 + c] * rs;
        d_dv[o] = (b1[o] - m) * rs + be1[o];
    }
}

// ---------------- prefix sum -> CSR rowstart/cursor ----------------
__global__ void k_scan() {
    __shared__ int bufA[2048], bufB[2048];
    int t = threadIdx.x;  // 1024 threads
    bufA[t] = d_cnt[t]; bufA[t + 1024] = d_cnt[t + 1024];
    __syncthreads();
    int* src = bufA; int* dst = bufB;
    for (int off = 1; off < 2048; off <<= 1) {
        for (int i = t; i < 2048; i += 1024) {
            int v = src[i];
            if (i >= off) v += src[i - off];
            dst[i] = v;
        }
        __syncthreads();
        int* tmp = src; src = dst; dst = tmp;
    }
    for (int i = t; i < 2048; i += 1024) {
        int ex = (i == 0) ? 0 : src[i - 1];
        d_rowstart[i] = ex; d_cursor[i] = ex;
    }
    if (t == 0) d_rowstart[2048] = src[2047];
}

// ---------------- scatter edges into CSR ----------------
__global__ void k_scatter(const int* __restrict__ ei) {
    int i = blockIdx.x * blockDim.x + threadIdx.x;
    if (i < NN) {
        int pos = atomicAdd(&d_cursor[i], 1);
        d_esrc[pos] = i;
    } else if (i < NN + EE) {
        int e = i - NN;
        int s = ei[e], d = ei[EE + e];
        if (s != d) { int pos = atomicAdd(&d_cursor[d], 1); d_esrc[pos] = s; }
    }
}

// ---------------- fused conv1+BN1 apply -> split-bf16 Acat ----------------
__global__ __launch_bounds__(256) void k_yf(const float* __restrict__ x) {
    __shared__ float As[256], dvs[16];
    int t = threadIdx.x;
    if (t < 256) As[t] = d_A[t];
    if (t < 16) dvs[t] = d_dv[t];
    __syncthreads();
    int q = blockIdx.x * 256 + t;   // pixel id, 131072 total
    int n = q >> 6, p = q & 63;
    float xv[16];
    #pragma unroll
    for (int c = 0; c < 16; c++) xv[c] = x[n * 1024 + c * 64 + p];
    #pragma unroll
    for (int o = 0; o < 16; o++) {
        float s = dvs[o];
        #pragma unroll
        for (int c = 0; c < 16; c++) s += As[o * 16 + c] * xv[c];
        int f = o * 64 + p;
        __nv_bfloat16 hi = __float2bfloat16(s);
        __nv_bfloat16 lo = __float2bfloat16(s - __bfloat162float(hi));
        size_t base = (size_t)n * KCAT + f;
        d_Acat[base] = hi;
        d_Acat[base + 1024] = hi;
        d_Acat[base + 2048] = lo;
    }
}

// ---------------- transpose + split-convert weights: w[1024][4096] -> Bcat[4096][3072] ----------------
__global__ __launch_bounds__(256) void k_convB(const float* __restrict__ w,
                                               __nv_bfloat16* __restrict__ Bcat) {
    __shared__ float ts[32][33];
    int t = threadIdx.x;
    int nb = blockIdx.x * 32;   // n tile (4096/32 = 128)
    int kb = blockIdx.y * 32;   // k tile (1024/32 = 32)
    int col = t & 31, trow = t >> 5;
    #pragma unroll
    for (int i = 0; i < 4; i++) {
        int r = trow + i * 8;
        ts[r][col] = w[(size_t)(kb + r) * 4096 + nb + col];
    }
    __syncthreads();
    int nloc = t >> 3, kq = (t & 7) * 4;
    __nv_bfloat16 hi[4], lo[4];
    #pragma unroll
    for (int j = 0; j < 4; j++) {
        float v = ts[kq + j][nloc];
        hi[j] = __float2bfloat16(v);
        lo[j] = __float2bfloat16(v - __bfloat162float(hi[j]));
    }
    size_t base = (size_t)(nb + nloc) * KCAT + kb + kq;
    *(uint2*)(Bcat + base)        = *(uint2*)hi;   // Bhi
    *(uint2*)(Bcat + base + 1024) = *(uint2*)lo;   // Blo
    *(uint2*)(Bcat + base + 2048) = *(uint2*)hi;   // Bhi
}

// ---------------- mma.sync bf16x3 GEMM: C[2048,4096] = Acat @ Bcat^T + bias ----------------
// CTA tile 128x256, 512 thr (4x4 warps, warp tile 32x64), K chunks of 64, 2-stage cp.async
#define STAGE_B 49152
#define GSM_TOTAL (2 * STAGE_B)

#define ISSUE_CHUNK(kb, buf) do {                                               \
    uint32_t sA_ = sbase + (buf) * STAGE_B;                                     \
    uint32_t sB_ = sA_ + 16384;                                                 \
    _Pragma("unroll")                                                           \
    for (int i_ = 0; i_ < 2; i_++) {                                            \
        int id_ = t + i_ * 512, r_ = id_ >> 3, c_ = id_ & 7;                    \
        cp16(sA_ + r_ * 128 + ((c_ ^ (r_ & 7)) << 4),                           \
             Ag + (size_t)r_ * KCAT + (kb) * 64 + c_ * 8);                      \
    }                                                                           \
    _Pragma("unroll")                                                           \
    for (int i_ = 0; i_ < 4; i_++) {                                            \
        int id_ = t + i_ * 512, r_ = id_ >> 3, c_ = id_ & 7;                    \
        cp16(sB_ + r_ * 128 + ((c_ ^ (r_ & 7)) << 4),                           \
             Bg + (size_t)r_ * KCAT + (kb) * 64 + c_ * 8);                      \
    }                                                                           \
    asm volatile("cp.async.commit_group;" ::: "memory");                        \
} while (0)

__global__ __launch_bounds__(512) void k_gemm(const __nv_bfloat16* __restrict__ Bmat,
                                              const float* __restrict__ bias,
                                              float* __restrict__ C) {
    extern __shared__ char smem[];
    uint32_t sbase = smem_u32(smem);
    int t = threadIdx.x, lane = t & 31, wid = t >> 5;
    int wm = wid & 3, wn = wid >> 2;            // 4 warp-rows (M) x 4 warp-cols (N)
    int bm = blockIdx.y * 128, bn = blockIdx.x * 256;

    const __nv_bfloat16* Ag = d_Acat + (size_t)bm * KCAT;
    const __nv_bfloat16* Bg = Bmat + (size_t)bn * KCAT;

    float acc[2][8][4];
    #pragma unroll
    for (int mi = 0; mi < 2; mi++)
        #pragma unroll
        for (int nj = 0; nj < 8; nj++)
            #pragma unroll
            for (int k = 0; k < 4; k++) acc[mi][nj][k] = 0.f;

    ISSUE_CHUNK(0, 0);
    ISSUE_CHUNK(1, 1);

    int g = lane >> 3, li = lane & 7;
    for (int kb = 0; kb < 48; kb++) {
        asm volatile("cp.async.wait_group 1;" ::: "memory");
        __syncthreads();
        uint32_t sA = sbase + (kb & 1) * STAGE_B;
        uint32_t sB = sA + 16384;
        #pragma unroll
        for (int ks = 0; ks < 4; ks++) {
            uint32_t af[2][4], bf[4][4];
            #pragma unroll
            for (int mi = 0; mi < 2; mi++) {
                int row = wm * 32 + mi * 16 + (g & 1) * 8 + li;
                int unit = ks * 2 + (g >> 1);
                ldm4(af[mi], sA + row * 128 + ((unit ^ (row & 7)) << 4));
            }
            #pragma unroll
            for (int nt = 0; nt < 4; nt++) {
                int row = wn * 64 + nt * 16 + (g >> 1) * 8 + li;  // n index
                int unit = ks * 2 + (g & 1);
                ldm4(bf[nt], sB + row * 128 + ((unit ^ (row & 7)) << 4));
            }
            #pragma unroll
            for (int mi = 0; mi < 2; mi++)
                #pragma unroll
                for (int nt = 0; nt < 4; nt++) {
                    mma16816(acc[mi][nt * 2 + 0], af[mi], bf[nt][0], bf[nt][1]);
                    mma16816(acc[mi][nt * 2 + 1], af[mi], bf[nt][2], bf[nt][3]);
                }
        }
        __syncthreads();
        if (kb + 2 < 48) { ISSUE_CHUNK(kb + 2, kb & 1); }
        else { asm volatile("cp.async.commit_group;" ::: "memory"); }
    }

    // epilogue: bias add + fp32 store
    #pragma unroll
    for (int mi = 0; mi < 2; mi++) {
        int gm0 = bm + wm * 32 + mi * 16 + (lane >> 2);
        #pragma unroll
        for (int nj = 0; nj < 8; nj++) {
            int gn = bn + wn * 64 + nj * 8 + (lane & 3) * 2;
            float2 bv = *(const float2*)(bias + gn);
            float2 o0, o1;
            o0.x = acc[mi][nj][0] + bv.x; o0.y = acc[mi][nj][1] + bv.y;
            o1.x = acc[mi][nj][2] + bv.x; o1.y = acc[mi][nj][3] + bv.y;
            *(float2*)(C + (size_t)gm0 * 4096 + gn) = o0;
            *(float2*)(C + (size_t)(gm0 + 8) * 4096 + gn) = o1;
        }
    }
}

// ---------------- fused GAT (online softmax) + conv2 + BN2 stats ----------------
__global__ __launch_bounds__(256) void k_gat(const float* __restrict__ att,
                                             const float* __restrict__ biasg,
                                             const float* __restrict__ w2,
                                             const float* __restrict__ b2,
                                             float* __restrict__ outp) {
    __shared__ float gs[4096];
    __shared__ float w2s[1024];
    __shared__ float red[8][4];
    __shared__ float logit_s[4];
    __shared__ float ssum[16], ssq[16];
    int n = blockIdx.x;
    int t = threadIdx.x;
    int lane = t & 31, warp = t >> 5;

    for (int i = t; i < 1024; i += 256) w2s[i] = w2[i];
    if (t < 16) { ssum[t] = 0.f; ssq[t] = 0.f; }

    float attv[16], xrv[16], acc[16];
    #pragma unroll
    for (int j = 0; j < 16; j++) {
        attv[j] = att[t + 256 * j];
        xrv[j]  = d_xr[n * 4096 + t + 256 * j];
        acc[j]  = 0.f;
    }
    float mh[4] = {-3.0e38f, -3.0e38f, -3.0e38f, -3.0e38f};
    float lh[4] = {0.f, 0.f, 0.f, 0.f};

    int beg = d_rowstart[n], end = d_rowstart[n + 1];
    for (int e = beg; e < end; e++) {
        int src = d_esrc[e];
        const float* xls = d_xl + src * 4096;
        float xlv[16];
        #pragma unroll
        for (int j = 0; j < 16; j++) xlv[j] = xls[t + 256 * j];

        float part[4] = {0.f, 0.f, 0.f, 0.f};
        #pragma unroll
        for (int j = 0; j < 16; j++) {
            float z = xlv[j] + xrv[j];
            float lr = z > 0.f ? z : 0.2f * z;
            part[j >> 2] += attv[j] * lr;
        }
        #pragma unroll
        for (int off = 16; off > 0; off >>= 1) {
            #pragma unroll
            for (int h = 0; h < 4; h++)
                part[h] += __shfl_down_sync(0xffffffffu, part[h], off);
        }
        if (lane == 0) {
            #pragma unroll
            for (int h = 0; h < 4; h++) red[warp][h] = part[h];
        }
        __syncthreads();
        if (t < 4) {
            float v = 0.f;
            #pragma unroll
            for (int w = 0; w < 8; w++) v += red[w][t];
            logit_s[t] = v;
        }
        __syncthreads();
        float sc[4], cf[4];
        #pragma unroll
        for (int h = 0; h < 4; h++) {
            float L = logit_s[h];
            float nm = fmaxf(mh[h], L);
            sc[h] = __expf(mh[h] - nm);
            cf[h] = __expf(L - nm);
            mh[h] = nm;
            lh[h] = lh[h] * sc[h] + cf[h];
        }
        #pragma unroll
        for (int j = 0; j < 16; j++)
            acc[j] = acc[j] * sc[j >> 2] + cf[j >> 2] * xlv[j];
    }

    #pragma unroll
    for (int j = 0; j < 16; j++) {
        float g = acc[j] / lh[j >> 2] + biasg[t + 256 * j];
        gs[t + 256 * j] = g;
    }
    __syncthreads();

    #pragma unroll
    for (int i = 0; i < 4; i++) {
        int oidx = t + 256 * i;
        int c = oidx >> 6, p = oidx & 63;
        float s = b2[c];
        #pragma unroll 16
        for (int ch = 0; ch < 64; ch++) s += w2s[c * 64 + ch] * gs[ch * 64 + p];
        outp[n * 1024 + oidx] = s;
        float vs = s, vq = s * s;
        #pragma unroll
        for (int off = 16; off > 0; off >>= 1) {
            vs += __shfl_down_sync(0xffffffffu, vs, off);
            vq += __shfl_down_sync(0xffffffffu, vq, off);
        }
        if (lane == 0) { atomicAdd(&ssum[c], vs); atomicAdd(&ssq[c], vq); }
    }
    __syncthreads();
    if (t < 16) {
        atomicAdd(&d_b2sum[t], ssum[t]);
        atomicAdd(&d_b2sq[t], ssq[t]);
    }
}

// ---------------- BN2 finalize ----------------
__global__ void k_bn2fin(const float* __restrict__ g2, const float* __restrict__ be2) {
    int t = threadIdx.x;
    if (t < 16) {
        float mean = d_b2sum[t] * (1.0f / NPIX);
        float var = d_b2sq[t] * (1.0f / NPIX) - mean * mean;
        float sc = g2[t] * rsqrtf(var + BNEPS);
        d_sc2[t] = sc;
        d_sh2[t] = be2[t] - mean * sc;
    }
}

// ---------------- apply BN2 + residual ----------------
__global__ void k_final(const float* __restrict__ x, float* __restrict__ o) {
    int i = blockIdx.x * blockDim.x + threadIdx.x;
    if (i < NN * 1024) {
        int c = (i >> 6) & 15;
        o[i] = o[i] * d_sc2[c] + d_sh2[c] + x[i];
    }
}

// ---------------- launch ----------------
extern "C" void kernel_launch(void* const* d_in, const int* in_sizes, int n_in,
                              void* d_out, int out_size) {
    const float* x    = (const float*)d_in[0];
    const int*   ei   = (const int*)  d_in[1];
    const float* w1   = (const float*)d_in[2];
    const float* b1   = (const float*)d_in[3];
    const float* g1   = (const float*)d_in[4];
    const float* be1  = (const float*)d_in[5];
    const float* wl   = (const float*)d_in[6];
    const float* bl   = (const float*)d_in[7];
    const float* wr   = (const float*)d_in[8];
    const float* br   = (const float*)d_in[9];
    const float* att  = (const float*)d_in[10];
    const float* bg   = (const float*)d_in[11];
    const float* w2   = (const float*)d_in[12];
    const float* b2   = (const float*)d_in[13];
    const float* g2   = (const float*)d_in[14];
    const float* be2  = (const float*)d_in[15];
    float* outp = (float*)d_out;

    cudaFuncSetAttribute(k_gemm, cudaFuncAttributeMaxDynamicSharedMemorySize, GSM_TOTAL);

    float* d_xl_p; cudaGetSymbolAddress((void**)&d_xl_p, d_xl);
    float* d_xr_p; cudaGetSymbolAddress((void**)&d_xr_p, d_xr);
    __nv_bfloat16* d_Bl_p; cudaGetSymbolAddress((void**)&d_Bl_p, d_Bl);
    __nv_bfloat16* d_Br_p; cudaGetSymbolAddress((void**)&d_Br_p, d_Br);

    k_init<<<1, 256>>>();
    k_stats<<<256, 256>>>(x);
    k_hist<<<64, 256>>>(ei);
    k_bnfold<<<1, 256>>>(w1, b1, g1, be1);
    k_scan<<<1, 1024>>>();
    k_scatter<<<(NN + EE + 255) / 256, 256>>>(ei);
    k_yf<<<512, 256>>>(x);
    dim3 gcv(128, 32);
    k_convB<<<gcv, 256>>>(wl, d_Bl_p);
    k_convB<<<gcv, 256>>>(wr, d_Br_p);
    dim3 gg(16, 16);   // 4096/256 N-tiles x 2048/128 M-tiles
    k_gemm<<<gg, 512, GSM_TOTAL>>>(d_Bl_p, bl, d_xl_p);
    k_gemm<<<gg, 512, GSM_TOTAL>>>(d_Br_p, br, d_xr_p);
    k_gat<<<NN, 256>>>(att, bg, w2, b2, outp);
    k_bn2fin<<<1, 32>>>(g2, be2);
    k_final<<<8192, 256>>>(x, outp);
}

// round 6
// speedup vs baseline: 3.8956x; 1.7224x over previous
#include <cuda_runtime.h>
#include <cuda_bf16.h>
#include <cuda_fp16.h>
#include <math.h>
#include <cstdint>

#define NN 2048
#define CC 16
#define FF 1024
#define NHEADS 4
#define KF 4096
#define EE 16384
#define NPIX 131072
#define BNEPS 1e-5f
#define KA 1024

// ---------------- scratch (static device memory; no allocation) ----------------
__device__ __half d_Af[NN * KA];                 // 4 MB   fp16 node features
__device__ __half d_Blh[KF * KA];                // 8 MB   fp16 transposed wl
__device__ __half d_Brh[KF * KA];                // 8 MB   fp16 transposed wr
__device__ float d_xl[NN * KF];                  // 33.5MB xl = yf@wl+bl
__device__ float d_xr[NN * KF];                  // 33.5MB xr = yf@wr+br
__device__ float d_Sx[16];
__device__ float d_Sxx[136];
__device__ float d_A[256];
__device__ float d_dv[16];
__device__ int   d_cnt[NN];
__device__ int   d_rowstart[NN + 1];
__device__ int   d_cursor[NN];
__device__ int   d_esrc[EE + NN];
__device__ float d_b2sum[16], d_b2sq[16], d_sc2[16], d_sh2[16];

// ---------------- helpers (all baseline sm_80+ PTX; no arch-'a' features) ----------------
__device__ __forceinline__ uint32_t smem_u32(const void* p) {
    uint32_t a;
    asm("{ .reg .u64 t; cvta.to.shared.u64 t, %1; cvt.u32.u64 %0, t; }" : "=r"(a) : "l"(p));
    return a;
}
__device__ __forceinline__ void cp16(uint32_t dst, const void* src) {
    asm volatile("cp.async.cg.shared.global [%0], [%1], 16;" :: "r"(dst), "l"(src) : "memory");
}
__device__ __forceinline__ void ldm4(uint32_t* r, uint32_t addr) {
    asm volatile("ldmatrix.sync.aligned.m8n8.x4.shared.b16 {%0,%1,%2,%3}, [%4];"
                 : "=r"(r[0]), "=r"(r[1]), "=r"(r[2]), "=r"(r[3]) : "r"(addr));
}
__device__ __forceinline__ void mma16816(float* d, const uint32_t* a, uint32_t b0, uint32_t b1) {
    asm volatile("mma.sync.aligned.m16n8k16.row.col.f32.f16.f16.f32 "
                 "{%0,%1,%2,%3}, {%4,%5,%6,%7}, {%8,%9}, {%0,%1,%2,%3};"
                 : "+f"(d[0]), "+f"(d[1]), "+f"(d[2]), "+f"(d[3])
                 : "r"(a[0]), "r"(a[1]), "r"(a[2]), "r"(a[3]), "r"(b0), "r"(b1));
}

// ---------------- init / zero accumulators ----------------
__global__ void k_init() {
    int t = threadIdx.x;
    for (int i = t; i < NN; i += 256) d_cnt[i] = 1;     // self-loop
    if (t < 16) { d_Sx[t] = 0.f; d_b2sum[t] = 0.f; d_b2sq[t] = 0.f; }
    for (int i = t; i < 136; i += 256) d_Sxx[i] = 0.f;
}

// ---------------- channel stats of x (for analytic BN1 fold) ----------------
__global__ __launch_bounds__(256) void k_stats(const float* __restrict__ x) {
    __shared__ float sm[16][513];
    int t = threadIdx.x;
    int base = blockIdx.x * 512;
    for (int i = t; i < 16 * 512; i += 256) {
        int c = i >> 9, s = i & 511;
        int q = base + s;
        sm[c][s] = x[(q >> 6) * 1024 + c * 64 + (q & 63)];
    }
    __syncthreads();
    if (t < 16) {
        float acc = 0.f;
        #pragma unroll 8
        for (int s = 0; s < 512; s++) acc += sm[t][s];
        atomicAdd(&d_Sx[t], acc);
    } else if (t < 152) {
        int p = t - 16;
        int c = 0, r = p;
        while (r >= 16 - c) { r -= 16 - c; c++; }
        int c2 = c + r;
        float acc = 0.f;
        #pragma unroll 8
        for (int s = 0; s < 512; s++) acc += sm[c][s] * sm[c2][s];
        atomicAdd(&d_Sxx[p], acc);
    }
}

// ---------------- edge histogram ----------------
__global__ void k_hist(const int* __restrict__ ei) {
    int e = blockIdx.x * blockDim.x + threadIdx.x;
    if (e < EE) {
        int s = ei[e], d = ei[EE + e];
        if (s != d) atomicAdd(&d_cnt[d], 1);
    }
}

// ---------------- fold conv1+BN1 into affine A, dv ----------------
__global__ void k_bnfold(const float* __restrict__ w1, const float* __restrict__ b1,
                         const float* __restrict__ g1, const float* __restrict__ be1) {
    __shared__ float mx[16], cov[16][16];
    int t = threadIdx.x;
    if (t < 16) mx[t] = d_Sx[t] * (1.0f / NPIX);
    __syncthreads();
    if (t < 136) {
        int c = 0, r = t;
        while (r >= 16 - c) { r -= 16 - c; c++; }
        int c2 = c + r;
        float cv = d_Sxx[t] * (1.0f / NPIX) - mx[c] * mx[c2];
        cov[c][c2] = cv; cov[c2][c] = cv;
    }
    __syncthreads();
    if (t < 16) {
        int o = t;
        float m = b1[o], var = 0.f;
        for (int c = 0; c < 16; c++) {
            float wc = w1[o * 16 + c];
            m += wc * mx[c];
            for (int c2 = 0; c2 < 16; c2++) var += wc * w1[o * 16 + c2] * cov[c][c2];
        }
        float rs = rsqrtf(var + BNEPS) * g1[o];
        for (int c = 0; c < 16; c++) d_A[o * 16 + c] = w1[o * 16 + c] * rs;
        d_dv[o] = (b1[o] - m) * rs + be1[o];
    }
}

// ---------------- prefix sum -> CSR rowstart/cursor ----------------
__global__ void k_scan() {
    __shared__ int bufA[2048], bufB[2048];
    int t = threadIdx.x;  // 1024 threads
    bufA[t] = d_cnt[t]; bufA[t + 1024] = d_cnt[t + 1024];
    __syncthreads();
    int* src = bufA; int* dst = bufB;
    for (int off = 1; off < 2048; off <<= 1) {
        for (int i = t; i < 2048; i += 1024) {
            int v = src[i];
            if (i >= off) v += src[i - off];
            dst[i] = v;
        }
        __syncthreads();
        int* tmp = src; src = dst; dst = tmp;
    }
    for (int i = t; i < 2048; i += 1024) {
        int ex = (i == 0) ? 0 : src[i - 1];
        d_rowstart[i] = ex; d_cursor[i] = ex;
    }
    if (t == 0) d_rowstart[2048] = src[2047];
}

// ---------------- scatter edges into CSR ----------------
__global__ void k_scatter(const int* __restrict__ ei) {
    int i = blockIdx.x * blockDim.x + threadIdx.x;
    if (i < NN) {
        int pos = atomicAdd(&d_cursor[i], 1);
        d_esrc[pos] = i;
    } else if (i < NN + EE) {
        int e = i - NN;
        int s = ei[e], d = ei[EE + e];
        if (s != d) { int pos = atomicAdd(&d_cursor[d], 1); d_esrc[pos] = s; }
    }
}

// ---------------- fused conv1+BN1 apply -> fp16 A ----------------
__global__ __launch_bounds__(256) void k_yf(const float* __restrict__ x) {
    __shared__ float As[256], dvs[16];
    int t = threadIdx.x;
    if (t < 256) As[t] = d_A[t];
    if (t < 16) dvs[t] = d_dv[t];
    __syncthreads();
    int q = blockIdx.x * 256 + t;   // pixel id, 131072 total
    int n = q >> 6, p = q & 63;
    float xv[16];
    #pragma unroll
    for (int c = 0; c < 16; c++) xv[c] = x[n * 1024 + c * 64 + p];
    #pragma unroll
    for (int o = 0; o < 16; o++) {
        float s = dvs[o];
        #pragma unroll
        for (int c = 0; c < 16; c++) s += As[o * 16 + c] * xv[c];
        int f = o * 64 + p;
        d_Af[(size_t)n * KA + f] = __float2half(s);
    }
}

// ---------------- transpose + fp16 convert weights: w[1024][4096] -> Bf[4096][1024] ----------------
__global__ __launch_bounds__(256) void k_convB(const float* __restrict__ w,
                                               __half* __restrict__ Bf) {
    __shared__ float ts[32][33];
    int t = threadIdx.x;
    int nb = blockIdx.x * 32;   // n tile (4096/32 = 128)
    int kb = blockIdx.y * 32;   // k tile (1024/32 = 32)
    int col = t & 31, trow = t >> 5;
    #pragma unroll
    for (int i = 0; i < 4; i++) {
        int r = trow + i * 8;
        ts[r][col] = w[(size_t)(kb + r) * 4096 + nb + col];
    }
    __syncthreads();
    int nloc = t >> 3, kq = (t & 7) * 4;
    __half hv[4];
    #pragma unroll
    for (int j = 0; j < 4; j++) hv[j] = __float2half(ts[kq + j][nloc]);
    size_t base = (size_t)(nb + nloc) * KA + kb + kq;
    *(uint2*)(Bf + base) = *(uint2*)hv;
}

// ---------------- mma.sync fp16 GEMM (merged L+R): C[2048,4096] = A @ B^T + bias ----------------
// CTA tile 128x256, 512 thr (4x4 warps, warp tile 32x64), K=1024 in chunks of 64, 2-stage cp.async
#define STAGE_B 49152
#define GSM_TOTAL (2 * STAGE_B)

#define ISSUE_CHUNK(kb, buf) do {                                               \
    uint32_t sA_ = sbase + (buf) * STAGE_B;                                     \
    uint32_t sB_ = sA_ + 16384;                                                 \
    _Pragma("unroll")                                                           \
    for (int i_ = 0; i_ < 2; i_++) {                                            \
        int id_ = t + i_ * 512, r_ = id_ >> 3, c_ = id_ & 7;                    \
        cp16(sA_ + r_ * 128 + ((c_ ^ (r_ & 7)) << 4),                           \
             Ag + (size_t)r_ * KA + (kb) * 64 + c_ * 8);                        \
    }                                                                           \
    _Pragma("unroll")                                                           \
    for (int i_ = 0; i_ < 4; i_++) {                                            \
        int id_ = t + i_ * 512, r_ = id_ >> 3, c_ = id_ & 7;                    \
        cp16(sB_ + r_ * 128 + ((c_ ^ (r_ & 7)) << 4),                           \
             Bg + (size_t)r_ * KA + (kb) * 64 + c_ * 8);                        \
    }                                                                           \
    asm volatile("cp.async.commit_group;" ::: "memory");                        \
} while (0)

__global__ __launch_bounds__(512) void k_gemm(const float* __restrict__ biasl,
                                              const float* __restrict__ biasr) {
    extern __shared__ char smem[];
    uint32_t sbase = smem_u32(smem);
    int t = threadIdx.x, lane = t & 31, wid = t >> 5;
    int wm = wid & 3, wn = wid >> 2;            // 4 warp-rows (M) x 4 warp-cols (N)
    int bm = blockIdx.y * 128;
    int bx = blockIdx.x;
    int isR = bx >= 16;
    int bn = (bx - (isR ? 16 : 0)) * 256;

    const __half* Ag = d_Af + (size_t)bm * KA;
    const __half* Bg = (isR ? d_Brh : d_Blh) + (size_t)bn * KA;
    const float* bias = (isR ? biasr : biasl) + bn;
    float* C = isR ? d_xr : d_xl;

    float acc[2][8][4];
    #pragma unroll
    for (int mi = 0; mi < 2; mi++)
        #pragma unroll
        for (int nj = 0; nj < 8; nj++)
            #pragma unroll
            for (int k = 0; k < 4; k++) acc[mi][nj][k] = 0.f;

    ISSUE_CHUNK(0, 0);
    ISSUE_CHUNK(1, 1);

    int g = lane >> 3, li = lane & 7;
    for (int kb = 0; kb < 16; kb++) {
        asm volatile("cp.async.wait_group 1;" ::: "memory");
        __syncthreads();
        uint32_t sA = sbase + (kb & 1) * STAGE_B;
        uint32_t sB = sA + 16384;
        #pragma unroll
        for (int ks = 0; ks < 4; ks++) {
            uint32_t af[2][4], bf[4][4];
            #pragma unroll
            for (int mi = 0; mi < 2; mi++) {
                int row = wm * 32 + mi * 16 + (g & 1) * 8 + li;
                int unit = ks * 2 + (g >> 1);
                ldm4(af[mi], sA + row * 128 + ((unit ^ (row & 7)) << 4));
            }
            #pragma unroll
            for (int nt = 0; nt < 4; nt++) {
                int row = wn * 64 + nt * 16 + (g >> 1) * 8 + li;  // n index
                int unit = ks * 2 + (g & 1);
                ldm4(bf[nt], sB + row * 128 + ((unit ^ (row & 7)) << 4));
            }
            #pragma unroll
            for (int mi = 0; mi < 2; mi++)
                #pragma unroll
                for (int nt = 0; nt < 4; nt++) {
                    mma16816(acc[mi][nt * 2 + 0], af[mi], bf[nt][0], bf[nt][1]);
                    mma16816(acc[mi][nt * 2 + 1], af[mi], bf[nt][2], bf[nt][3]);
                }
        }
        __syncthreads();
        if (kb + 2 < 16) { ISSUE_CHUNK(kb + 2, kb & 1); }
        else { asm volatile("cp.async.commit_group;" ::: "memory"); }
    }

    // epilogue: bias add + fp32 store
    #pragma unroll
    for (int mi = 0; mi < 2; mi++) {
        int gm0 = bm + wm * 32 + mi * 16 + (lane >> 2);
        #pragma unroll
        for (int nj = 0; nj < 8; nj++) {
            int gn = bn + wn * 64 + nj * 8 + (lane & 3) * 2;
            float2 bv = *(const float2*)(bias - bn + gn);
            float2 o0, o1;
            o0.x = acc[mi][nj][0] + bv.x; o0.y = acc[mi][nj][1] + bv.y;
            o1.x = acc[mi][nj][2] + bv.x; o1.y = acc[mi][nj][3] + bv.y;
            *(float2*)(C + (size_t)gm0 * 4096 + gn) = o0;
            *(float2*)(C + (size_t)(gm0 + 8) * 4096 + gn) = o1;
        }
    }
}

// ---------------- fused GAT (online softmax) + conv2 + BN2 stats ----------------
__global__ __launch_bounds__(256) void k_gat(const float* __restrict__ att,
                                             const float* __restrict__ biasg,
                                             const float* __restrict__ w2,
                                             const float* __restrict__ b2,
                                             float* __restrict__ outp) {
    __shared__ float gs[4096];
    __shared__ float w2s[1024];
    __shared__ float red[8][4];
    __shared__ float logit_s[4];
    __shared__ float ssum[16], ssq[16];
    int n = blockIdx.x;
    int t = threadIdx.x;
    int lane = t & 31, warp = t >> 5;

    for (int i = t; i < 1024; i += 256) w2s[i] = w2[i];
    if (t < 16) { ssum[t] = 0.f; ssq[t] = 0.f; }

    float attv[16], xrv[16], acc[16];
    #pragma unroll
    for (int j = 0; j < 16; j++) {
        attv[j] = att[t + 256 * j];
        xrv[j]  = d_xr[n * 4096 + t + 256 * j];
        acc[j]  = 0.f;
    }
    float mh[4] = {-3.0e38f, -3.0e38f, -3.0e38f, -3.0e38f};
    float lh[4] = {0.f, 0.f, 0.f, 0.f};

    int beg = d_rowstart[n], end = d_rowstart[n + 1];
    for (int e = beg; e < end; e++) {
        int src = d_esrc[e];
        const float* xls = d_xl + src * 4096;
        float xlv[16];
        #pragma unroll
        for (int j = 0; j < 16; j++) xlv[j] = xls[t + 256 * j];

        float part[4] = {0.f, 0.f, 0.f, 0.f};
        #pragma unroll
        for (int j = 0; j < 16; j++) {
            float z = xlv[j] + xrv[j];
            float lr = z > 0.f ? z : 0.2f * z;
            part[j >> 2] += attv[j] * lr;
        }
        #pragma unroll
        for (int off = 16; off > 0; off >>= 1) {
            #pragma unroll
            for (int h = 0; h < 4; h++)
                part[h] += __shfl_down_sync(0xffffffffu, part[h], off);
        }
        if (lane == 0) {
            #pragma unroll
            for (int h = 0; h < 4; h++) red[warp][h] = part[h];
        }
        __syncthreads();
        if (t < 4) {
            float v = 0.f;
            #pragma unroll
            for (int w = 0; w < 8; w++) v += red[w][t];
            logit_s[t] = v;
        }
        __syncthreads();
        float sc[4], cf[4];
        #pragma unroll
        for (int h = 0; h < 4; h++) {
            float L = logit_s[h];
            float nm = fmaxf(mh[h], L);
            sc[h] = __expf(mh[h] - nm);
            cf[h] = __expf(L - nm);
            mh[h] = nm;
            lh[h] = lh[h] * sc[h] + cf[h];
        }
        #pragma unroll
        for (int j = 0; j < 16; j++)
            acc[j] = acc[j] * sc[j >> 2] + cf[j >> 2] * xlv[j];
    }

    #pragma unroll
    for (int j = 0; j < 16; j++) {
        float g = acc[j] / lh[j >> 2] + biasg[t + 256 * j];
        gs[t + 256 * j] = g;
    }
    __syncthreads();

    #pragma unroll
    for (int i = 0; i < 4; i++) {
        int oidx = t + 256 * i;
        int c = oidx >> 6, p = oidx & 63;
        float s = b2[c];
        #pragma unroll 16
        for (int ch = 0; ch < 64; ch++) s += w2s[c * 64 + ch] * gs[ch * 64 + p];
        outp[n * 1024 + oidx] = s;
        float vs = s, vq = s * s;
        #pragma unroll
        for (int off = 16; off > 0; off >>= 1) {
            vs += __shfl_down_sync(0xffffffffu, vs, off);
            vq += __shfl_down_sync(0xffffffffu, vq, off);
        }
        if (lane == 0) { atomicAdd(&ssum[c], vs); atomicAdd(&ssq[c], vq); }
    }
    __syncthreads();
    if (t < 16) {
        atomicAdd(&d_b2sum[t], ssum[t]);
        atomicAdd(&d_b2sq[t], ssq[t]);
    }
}

// ---------------- BN2 finalize ----------------
__global__ void k_bn2fin(const float* __restrict__ g2, const float* __restrict__ be2) {
    int t = threadIdx.x;
    if (t < 16) {
        float mean = d_b2sum[t] * (1.0f / NPIX);
        float var = d_b2sq[t] * (1.0f / NPIX) - mean * mean;
        float sc = g2[t] * rsqrtf(var + BNEPS);
        d_sc2[t] = sc;
        d_sh2[t] = be2[t] - mean * sc;
    }
}

// ---------------- apply BN2 + residual ----------------
__global__ void k_final(const float* __restrict__ x, float* __restrict__ o) {
    int i = blockIdx.x * blockDim.x + threadIdx.x;
    if (i < NN * 1024) {
        int c = (i >> 6) & 15;
        o[i] = o[i] * d_sc2[c] + d_sh2[c] + x[i];
    }
}

// ---------------- launch ----------------
extern "C" void kernel_launch(void* const* d_in, const int* in_sizes, int n_in,
                              void* d_out, int out_size) {
    const float* x    = (const float*)d_in[0];
    const int*   ei   = (const int*)  d_in[1];
    const float* w1   = (const float*)d_in[2];
    const float* b1   = (const float*)d_in[3];
    const float* g1   = (const float*)d_in[4];
    const float* be1  = (const float*)d_in[5];
    const float* wl   = (const float*)d_in[6];
    const float* bl   = (const float*)d_in[7];
    const float* wr   = (const float*)d_in[8];
    const float* br   = (const float*)d_in[9];
    const float* att  = (const float*)d_in[10];
    const float* bg   = (const float*)d_in[11];
    const float* w2   = (const float*)d_in[12];
    const float* b2   = (const float*)d_in[13];
    const float* g2   = (const float*)d_in[14];
    const float* be2  = (const float*)d_in[15];
    float* outp = (float*)d_out;

    cudaFuncSetAttribute(k_gemm, cudaFuncAttributeMaxDynamicSharedMemorySize, GSM_TOTAL);

    __half* d_Blh_p; cudaGetSymbolAddress((void**)&d_Blh_p, d_Blh);
    __half* d_Brh_p; cudaGetSymbolAddress((void**)&d_Brh_p, d_Brh);

    k_init<<<1, 256>>>();
    k_stats<<<256, 256>>>(x);
    k_hist<<<64, 256>>>(ei);
    k_bnfold<<<1, 256>>>(w1, b1, g1, be1);
    k_scan<<<1, 1024>>>();
    k_scatter<<<(NN + EE + 255) / 256, 256>>>(ei);
    k_yf<<<512, 256>>>(x);
    dim3 gcv(128, 32);
    k_convB<<<gcv, 256>>>(wl, d_Blh_p);
    k_convB<<<gcv, 256>>>(wr, d_Brh_p);
    dim3 gg(32, 16);   // x: 16 tiles for xl + 16 tiles for xr; y: 2048/128 M-tiles
    k_gemm<<<gg, 512, GSM_TOTAL>>>(bl, br);
    k_gat<<<NN, 256>>>(att, bg, w2, b2, outp);
    k_bn2fin<<<1, 32>>>(g2, be2);
    k_final<<<8192, 256>>>(x, outp);
}

// round 7
// speedup vs baseline: 4.1219x; 1.0581x over previous
#include <cuda_runtime.h>
#include <cuda_bf16.h>
#include <cuda_fp16.h>
#include <math.h>
#include <cstdint>

#define NN 2048
#define CC 16
#define FF 1024
#define NHEADS 4
#define KF 4096
#define EE 16384
#define NPIX 131072
#define BNEPS 1e-5f
#define KA 1024

// ---------------- scratch (static device memory; no allocation) ----------------
__device__ __half d_Af[NN * KA];                 // 4 MB   fp16 node features
__device__ __half d_Blh[KF * KA];                // 8 MB   fp16 transposed wl
__device__ __half d_Brh[KF * KA];                // 8 MB   fp16 transposed wr
__device__ __half d_xl[NN * KF];                 // 16.8MB xl = yf@wl+bl (fp16)
__device__ __half d_xr[NN * KF];                 // 16.8MB xr = yf@wr+br (fp16)
__device__ float d_Sx[16];
__device__ float d_Sxx[136];
__device__ float d_A[256];
__device__ float d_dv[16];
__device__ int   d_cnt[NN];
__device__ int   d_rowstart[NN + 1];
__device__ int   d_cursor[NN];
__device__ int   d_esrc[EE + NN];
__device__ float d_b2sum[16], d_b2sq[16], d_sc2[16], d_sh2[16];

// ---------------- helpers (all baseline sm_80+ PTX; no arch-'a' features) ----------------
__device__ __forceinline__ uint32_t smem_u32(const void* p) {
    uint32_t a;
    asm("{ .reg .u64 t; cvta.to.shared.u64 t, %1; cvt.u32.u64 %0, t; }" : "=r"(a) : "l"(p));
    return a;
}
__device__ __forceinline__ void cp16(uint32_t dst, const void* src) {
    asm volatile("cp.async.cg.shared.global [%0], [%1], 16;" :: "r"(dst), "l"(src) : "memory");
}
__device__ __forceinline__ void ldm4(uint32_t* r, uint32_t addr) {
    asm volatile("ldmatrix.sync.aligned.m8n8.x4.shared.b16 {%0,%1,%2,%3}, [%4];"
                 : "=r"(r[0]), "=r"(r[1]), "=r"(r[2]), "=r"(r[3]) : "r"(addr));
}
__device__ __forceinline__ void mma16816(float* d, const uint32_t* a, uint32_t b0, uint32_t b1) {
    asm volatile("mma.sync.aligned.m16n8k16.row.col.f32.f16.f16.f32 "
                 "{%0,%1,%2,%3}, {%4,%5,%6,%7}, {%8,%9}, {%0,%1,%2,%3};"
                 : "+f"(d[0]), "+f"(d[1]), "+f"(d[2]), "+f"(d[3])
                 : "r"(a[0]), "r"(a[1]), "r"(a[2]), "r"(a[3]), "r"(b0), "r"(b1));
}

// ---------------- init / zero accumulators ----------------
__global__ void k_init() {
    int t = threadIdx.x;
    for (int i = t; i < NN; i += 256) d_cnt[i] = 1;     // self-loop
    if (t < 16) { d_Sx[t] = 0.f; d_b2sum[t] = 0.f; d_b2sq[t] = 0.f; }
    for (int i = t; i < 136; i += 256) d_Sxx[i] = 0.f;
}

// ---------------- channel stats of x (for analytic BN1 fold) ----------------
__global__ __launch_bounds__(256) void k_stats(const float* __restrict__ x) {
    __shared__ float sm[16][513];
    int t = threadIdx.x;
    int base = blockIdx.x * 512;
    for (int i = t; i < 16 * 512; i += 256) {
        int c = i >> 9, s = i & 511;
        int q = base + s;
        sm[c][s] = x[(q >> 6) * 1024 + c * 64 + (q & 63)];
    }
    __syncthreads();
    if (t < 16) {
        float acc = 0.f;
        #pragma unroll 8
        for (int s = 0; s < 512; s++) acc += sm[t][s];
        atomicAdd(&d_Sx[t], acc);
    } else if (t < 152) {
        int p = t - 16;
        int c = 0, r = p;
        while (r >= 16 - c) { r -= 16 - c; c++; }
        int c2 = c + r;
        float acc = 0.f;
        #pragma unroll 8
        for (int s = 0; s < 512; s++) acc += sm[c][s] * sm[c2][s];
        atomicAdd(&d_Sxx[p], acc);
    }
}

// ---------------- edge histogram ----------------
__global__ void k_hist(const int* __restrict__ ei) {
    int e = blockIdx.x * blockDim.x + threadIdx.x;
    if (e < EE) {
        int s = ei[e], d = ei[EE + e];
        if (s != d) atomicAdd(&d_cnt[d], 1);
    }
}

// ---------------- fold conv1+BN1 into affine A, dv (parallel) ----------------
__global__ void k_bnfold(const float* __restrict__ w1, const float* __restrict__ b1,
                         const float* __restrict__ g1, const float* __restrict__ be1) {
    __shared__ float mx[16], cov[16][16];
    int t = threadIdx.x;
    if (t < 16) mx[t] = d_Sx[t] * (1.0f / NPIX);
    __syncthreads();
    if (t < 136) {
        int c = 0, r = t;
        while (r >= 16 - c) { r -= 16 - c; c++; }
        int c2 = c + r;
        float cv = d_Sxx[t] * (1.0f / NPIX) - mx[c] * mx[c2];
        cov[c][c2] = cv; cov[c2][c] = cv;
    }
    __syncthreads();
    // 256 threads: (o = t>>4, c = t&15)
    int o = t >> 4, c = t & 15;
    float wc = w1[o * 16 + c];
    float pm = wc * mx[c];
    float pv = 0.f;
    #pragma unroll
    for (int c2 = 0; c2 < 16; c2++) pv += w1[o * 16 + c2] * cov[c][c2];
    pv *= wc;
    #pragma unroll
    for (int off = 8; off > 0; off >>= 1) {
        pm += __shfl_down_sync(0xffffffffu, pm, off, 16);
        pv += __shfl_down_sync(0xffffffffu, pv, off, 16);
    }
    // broadcast sums to all 16 lanes of the group
    float m = __shfl_sync(0xffffffffu, pm, (t & 16), 32) + b1[o];
    float var = __shfl_sync(0xffffffffu, pv, (t & 16), 32);
    float rs = rsqrtf(var + BNEPS) * g1[o];
    d_A[o * 16 + c] = wc * rs;
    if (c == 0) d_dv[o] = (b1[o] - m) * rs + be1[o];
}

// ---------------- prefix sum -> CSR rowstart/cursor ----------------
__global__ void k_scan() {
    __shared__ int bufA[2048], bufB[2048];
    int t = threadIdx.x;  // 1024 threads
    bufA[t] = d_cnt[t]; bufA[t + 1024] = d_cnt[t + 1024];
    __syncthreads();
    int* src = bufA; int* dst = bufB;
    for (int off = 1; off < 2048; off <<= 1) {
        for (int i = t; i < 2048; i += 1024) {
            int v = src[i];
            if (i >= off) v += src[i - off];
            dst[i] = v;
        }
        __syncthreads();
        int* tmp = src; src = dst; dst = tmp;
    }
    for (int i = t; i < 2048; i += 1024) {
        int ex = (i == 0) ? 0 : src[i - 1];
        d_rowstart[i] = ex; d_cursor[i] = ex;
    }
    if (t == 0) d_rowstart[2048] = src[2047];
}

// ---------------- scatter edges into CSR ----------------
__global__ void k_scatter(const int* __restrict__ ei) {
    int i = blockIdx.x * blockDim.x + threadIdx.x;
    if (i < NN) {
        int pos = atomicAdd(&d_cursor[i], 1);
        d_esrc[pos] = i;
    } else if (i < NN + EE) {
        int e = i - NN;
        int s = ei[e], d = ei[EE + e];
        if (s != d) { int pos = atomicAdd(&d_cursor[d], 1); d_esrc[pos] = s; }
    }
}

// ---------------- fused conv1+BN1 apply -> fp16 A ----------------
__global__ __launch_bounds__(256) void k_yf(const float* __restrict__ x) {
    __shared__ float As[256], dvs[16];
    int t = threadIdx.x;
    if (t < 256) As[t] = d_A[t];
    if (t < 16) dvs[t] = d_dv[t];
    __syncthreads();
    int q = blockIdx.x * 256 + t;   // pixel id, 131072 total
    int n = q >> 6, p = q & 63;
    float xv[16];
    #pragma unroll
    for (int c = 0; c < 16; c++) xv[c] = x[n * 1024 + c * 64 + p];
    #pragma unroll
    for (int o = 0; o < 16; o++) {
        float s = dvs[o];
        #pragma unroll
        for (int c = 0; c < 16; c++) s += As[o * 16 + c] * xv[c];
        int f = o * 64 + p;
        d_Af[(size_t)n * KA + f] = __float2half(s);
    }
}

// ---------------- transpose + fp16 convert weights: w[1024][4096] -> Bf[4096][1024] ----------------
__global__ __launch_bounds__(256) void k_convB(const float* __restrict__ w,
                                               __half* __restrict__ Bf) {
    __shared__ float ts[32][33];
    int t = threadIdx.x;
    int nb = blockIdx.x * 32;   // n tile (4096/32 = 128)
    int kb = blockIdx.y * 32;   // k tile (1024/32 = 32)
    int col = t & 31, trow = t >> 5;
    #pragma unroll
    for (int i = 0; i < 4; i++) {
        int r = trow + i * 8;
        ts[r][col] = w[(size_t)(kb + r) * 4096 + nb + col];
    }
    __syncthreads();
    int nloc = t >> 3, kq = (t & 7) * 4;
    __half hv[4];
    #pragma unroll
    for (int j = 0; j < 4; j++) hv[j] = __float2half(ts[kq + j][nloc]);
    size_t base = (size_t)(nb + nloc) * KA + kb + kq;
    *(uint2*)(Bf + base) = *(uint2*)hv;
}

// ---------------- mma.sync fp16 GEMM (merged L+R): C[2048,4096] = A @ B^T + bias (fp16 out) ----------------
// CTA tile 128x256, 512 thr (4x4 warps, warp tile 32x64), K=1024 in chunks of 64, 3-stage cp.async
#define STAGE_B 49152
#define GSM_TOTAL (3 * STAGE_B)

#define ISSUE_CHUNK(kb, buf) do {                                               \
    uint32_t sA_ = sbase + (buf) * STAGE_B;                                     \
    uint32_t sB_ = sA_ + 16384;                                                 \
    _Pragma("unroll")                                                           \
    for (int i_ = 0; i_ < 2; i_++) {                                            \
        int id_ = t + i_ * 512, r_ = id_ >> 3, c_ = id_ & 7;                    \
        cp16(sA_ + r_ * 128 + ((c_ ^ (r_ & 7)) << 4),                           \
             Ag + (size_t)r_ * KA + (kb) * 64 + c_ * 8);                        \
    }                                                                           \
    _Pragma("unroll")                                                           \
    for (int i_ = 0; i_ < 4; i_++) {                                            \
        int id_ = t + i_ * 512, r_ = id_ >> 3, c_ = id_ & 7;                    \
        cp16(sB_ + r_ * 128 + ((c_ ^ (r_ & 7)) << 4),                           \
             Bg + (size_t)r_ * KA + (kb) * 64 + c_ * 8);                        \
    }                                                                           \
    asm volatile("cp.async.commit_group;" ::: "memory");                        \
} while (0)

__global__ __launch_bounds__(512) void k_gemm(const float* __restrict__ biasl,
                                              const float* __restrict__ biasr) {
    extern __shared__ char smem[];
    uint32_t sbase = smem_u32(smem);
    int t = threadIdx.x, lane = t & 31, wid = t >> 5;
    int wm = wid & 3, wn = wid >> 2;            // 4 warp-rows (M) x 4 warp-cols (N)
    int bm = blockIdx.y * 128;
    int bx = blockIdx.x;
    int isR = bx >= 16;
    int bn = (bx - (isR ? 16 : 0)) * 256;

    const __half* Ag = d_Af + (size_t)bm * KA;
    const __half* Bg = (isR ? d_Brh : d_Blh) + (size_t)bn * KA;
    const float* bias = isR ? biasr : biasl;
    __half* C = isR ? d_xr : d_xl;

    float acc[2][8][4];
    #pragma unroll
    for (int mi = 0; mi < 2; mi++)
        #pragma unroll
        for (int nj = 0; nj < 8; nj++)
            #pragma unroll
            for (int k = 0; k < 4; k++) acc[mi][nj][k] = 0.f;

    // 3-stage pipeline: prologue fills stages 0,1
    ISSUE_CHUNK(0, 0);
    ISSUE_CHUNK(1, 1);

    int g = lane >> 3, li = lane & 7;
    int buf = 0;
    for (int kb = 0; kb < 16; kb++) {
        asm volatile("cp.async.wait_group 1;" ::: "memory");   // stage kb ready
        __syncthreads();                                        // also fences buffer reuse
        // issue chunk kb+2 into buffer (kb+2)%3 == the one read in iteration kb-1
        if (kb + 2 < 16) {
            int nb_ = (kb + 2) % 3;
            ISSUE_CHUNK(kb + 2, nb_);
        } else {
            asm volatile("cp.async.commit_group;" ::: "memory");
        }
        uint32_t sA = sbase + buf * STAGE_B;
        uint32_t sB = sA + 16384;
        #pragma unroll
        for (int ks = 0; ks < 4; ks++) {
            uint32_t af[2][4], bf[4][4];
            #pragma unroll
            for (int mi = 0; mi < 2; mi++) {
                int row = wm * 32 + mi * 16 + (g & 1) * 8 + li;
                int unit = ks * 2 + (g >> 1);
                ldm4(af[mi], sA + row * 128 + ((unit ^ (row & 7)) << 4));
            }
            #pragma unroll
            for (int nt = 0; nt < 4; nt++) {
                int row = wn * 64 + nt * 16 + (g >> 1) * 8 + li;  // n index
                int unit = ks * 2 + (g & 1);
                ldm4(bf[nt], sB + row * 128 + ((unit ^ (row & 7)) << 4));
            }
            #pragma unroll
            for (int mi = 0; mi < 2; mi++)
                #pragma unroll
                for (int nt = 0; nt < 4; nt++) {
                    mma16816(acc[mi][nt * 2 + 0], af[mi], bf[nt][0], bf[nt][1]);
                    mma16816(acc[mi][nt * 2 + 1], af[mi], bf[nt][2], bf[nt][3]);
                }
        }
        buf = (buf + 1) % 3;
    }

    // epilogue: bias add + fp16 store
    #pragma unroll
    for (int mi = 0; mi < 2; mi++) {
        int gm0 = bm + wm * 32 + mi * 16 + (lane >> 2);
        #pragma unroll
        for (int nj = 0; nj < 8; nj++) {
            int gn = bn + wn * 64 + nj * 8 + (lane & 3) * 2;
            float2 bv = *(const float2*)(bias + gn);
            __half2 h0 = __floats2half2_rn(acc[mi][nj][0] + bv.x, acc[mi][nj][1] + bv.y);
            __half2 h1 = __floats2half2_rn(acc[mi][nj][2] + bv.x, acc[mi][nj][3] + bv.y);
            *(__half2*)(C + (size_t)gm0 * 4096 + gn) = h0;
            *(__half2*)(C + (size_t)(gm0 + 8) * 4096 + gn) = h1;
        }
    }
}

// ---------------- fused GAT (online softmax) + conv2 + BN2 stats ----------------
// feature mapping per thread: f_j = 2t + 512j (j=0..7); head(f_j) = j>>1
__global__ __launch_bounds__(256) void k_gat(const float* __restrict__ att,
                                             const float* __restrict__ biasg,
                                             const float* __restrict__ w2,
                                             const float* __restrict__ b2,
                                             float* __restrict__ outp) {
    __shared__ float gs[4096];
    __shared__ float w2s[1024];
    __shared__ float red[8][4];
    __shared__ float logit_s[4];
    __shared__ float ssum[16], ssq[16];
    int n = blockIdx.x;
    int t = threadIdx.x;
    int lane = t & 31, warp = t >> 5;

    for (int i = t; i < 1024; i += 256) w2s[i] = w2[i];
    if (t < 16) { ssum[t] = 0.f; ssq[t] = 0.f; }

    const __half2* xr2 = (const __half2*)d_xr + (size_t)n * 2048;
    float2 attv[8], xrv[8], acc[8];
    #pragma unroll
    for (int j = 0; j < 8; j++) {
        int f = 2 * t + 512 * j;
        attv[j] = *(const float2*)(att + f);
        xrv[j] = __half22float2(xr2[t + 256 * j]);
        acc[j] = make_float2(0.f, 0.f);
    }
    float mh[4] = {-3.0e38f, -3.0e38f, -3.0e38f, -3.0e38f};
    float lh[4] = {0.f, 0.f, 0.f, 0.f};

    int beg = d_rowstart[n], end = d_rowstart[n + 1];
    for (int e = beg; e < end; e++) {
        int src = d_esrc[e];
        const __half2* xls = (const __half2*)d_xl + (size_t)src * 2048;
        float2 xf[8];
        #pragma unroll
        for (int j = 0; j < 8; j++) xf[j] = __half22float2(xls[t + 256 * j]);

        float part[4] = {0.f, 0.f, 0.f, 0.f};
        #pragma unroll
        for (int j = 0; j < 8; j++) {
            float zx = xf[j].x + xrv[j].x;
            float zy = xf[j].y + xrv[j].y;
            float lx = zx > 0.f ? zx : 0.2f * zx;
            float ly = zy > 0.f ? zy : 0.2f * zy;
            part[j >> 1] += attv[j].x * lx + attv[j].y * ly;
        }
        #pragma unroll
        for (int off = 16; off > 0; off >>= 1) {
            #pragma unroll
            for (int h = 0; h < 4; h++)
                part[h] += __shfl_down_sync(0xffffffffu, part[h], off);
        }
        if (lane == 0) {
            #pragma unroll
            for (int h = 0; h < 4; h++) red[warp][h] = part[h];
        }
        __syncthreads();
        if (t < 4) {
            float v = 0.f;
            #pragma unroll
            for (int w = 0; w < 8; w++) v += red[w][t];
            logit_s[t] = v;
        }
        __syncthreads();
        float sc[4], cf[4];
        #pragma unroll
        for (int h = 0; h < 4; h++) {
            float L = logit_s[h];
            float nm = fmaxf(mh[h], L);
            sc[h] = __expf(mh[h] - nm);
            cf[h] = __expf(L - nm);
            mh[h] = nm;
            lh[h] = lh[h] * sc[h] + cf[h];
        }
        #pragma unroll
        for (int j = 0; j < 8; j++) {
            int h = j >> 1;
            acc[j].x = acc[j].x * sc[h] + cf[h] * xf[j].x;
            acc[j].y = acc[j].y * sc[h] + cf[h] * xf[j].y;
        }
    }

    #pragma unroll
    for (int j = 0; j < 8; j++) {
        int f = 2 * t + 512 * j;
        int h = j >> 1;
        float2 bgv = *(const float2*)(biasg + f);
        float2 g;
        g.x = acc[j].x / lh[h] + bgv.x;
        g.y = acc[j].y / lh[h] + bgv.y;
        *(float2*)(gs + f) = g;
    }
    __syncthreads();

    #pragma unroll
    for (int i = 0; i < 4; i++) {
        int oidx = t + 256 * i;
        int c = oidx >> 6, p = oidx & 63;
        float s = b2[c];
        #pragma unroll 16
        for (int ch = 0; ch < 64; ch++) s += w2s[c * 64 + ch] * gs[ch * 64 + p];
        outp[n * 1024 + oidx] = s;
        float vs = s, vq = s * s;
        #pragma unroll
        for (int off = 16; off > 0; off >>= 1) {
            vs += __shfl_down_sync(0xffffffffu, vs, off);
            vq += __shfl_down_sync(0xffffffffu, vq, off);
        }
        if (lane == 0) { atomicAdd(&ssum[c], vs); atomicAdd(&ssq[c], vq); }
    }
    __syncthreads();
    if (t < 16) {
        atomicAdd(&d_b2sum[t], ssum[t]);
        atomicAdd(&d_b2sq[t], ssq[t]);
    }
}

// ---------------- BN2 finalize ----------------
__global__ void k_bn2fin(const float* __restrict__ g2, const float* __restrict__ be2) {
    int t = threadIdx.x;
    if (t < 16) {
        float mean = d_b2sum[t] * (1.0f / NPIX);
        float var = d_b2sq[t] * (1.0f / NPIX) - mean * mean;
        float sc = g2[t] * rsqrtf(var + BNEPS);
        d_sc2[t] = sc;
        d_sh2[t] = be2[t] - mean * sc;
    }
}

// ---------------- apply BN2 + residual ----------------
__global__ void k_final(const float* __restrict__ x, float* __restrict__ o) {
    int i = blockIdx.x * blockDim.x + threadIdx.x;
    if (i < NN * 1024) {
        int c = (i >> 6) & 15;
        o[i] = o[i] * d_sc2[c] + d_sh2[c] + x[i];
    }
}

// ---------------- launch ----------------
extern "C" void kernel_launch(void* const* d_in, const int* in_sizes, int n_in,
                              void* d_out, int out_size) {
    const float* x    = (const float*)d_in[0];
    const int*   ei   = (const int*)  d_in[1];
    const float* w1   = (const float*)d_in[2];
    const float* b1   = (const float*)d_in[3];
    const float* g1   = (const float*)d_in[4];
    const float* be1  = (const float*)d_in[5];
    const float* wl   = (const float*)d_in[6];
    const float* bl   = (const float*)d_in[7];
    const float* wr   = (const float*)d_in[8];
    const float* br   = (const float*)d_in[9];
    const float* att  = (const float*)d_in[10];
    const float* bg   = (const float*)d_in[11];
    const float* w2   = (const float*)d_in[12];
    const float* b2   = (const float*)d_in[13];
    const float* g2   = (const float*)d_in[14];
    const float* be2  = (const float*)d_in[15];
    float* outp = (float*)d_out;

    cudaFuncSetAttribute(k_gemm, cudaFuncAttributeMaxDynamicSharedMemorySize, GSM_TOTAL);

    __half* d_Blh_p; cudaGetSymbolAddress((void**)&d_Blh_p, d_Blh);
    __half* d_Brh_p; cudaGetSymbolAddress((void**)&d_Brh_p, d_Brh);

    k_init<<<1, 256>>>();
    k_stats<<<256, 256>>>(x);
    k_hist<<<64, 256>>>(ei);
    k_bnfold<<<1, 256>>>(w1, b1, g1, be1);
    k_scan<<<1, 1024>>>();
    k_scatter<<<(NN + EE + 255) / 256, 256>>>(ei);
    k_yf<<<512, 256>>>(x);
    dim3 gcv(128, 32);
    k_convB<<<gcv, 256>>>(wl, d_Blh_p);
    k_convB<<<gcv, 256>>>(wr, d_Brh_p);
    dim3 gg(32, 16);   // x: 16 tiles for xl + 16 tiles for xr; y: 2048/128 M-tiles
    k_gemm<<<gg, 512, GSM_TOTAL>>>(bl, br);
    k_gat<<<NN, 256>>>(att, bg, w2, b2, outp);
    k_bn2fin<<<1, 32>>>(g2, be2);
    k_final<<<8192, 256>>>(x, outp);
}